// round 1
// baseline (speedup 1.0000x reference)
#include <cuda_runtime.h>
#include <math.h>

// Problem constants (fixed shapes from reference)
#define Bq   4
#define Nq   2048
#define DIN  128
#define Hq   4
#define HD   32
#define Kq   204          // int(0.1 * 2048)
#define BH   (Bq*Hq)      // 16

// Scratch (device globals; no allocation allowed)
__device__ float g_Wh[BH*Nq*HD];       // [b][h][n][d]  4 MB
__device__ float g_si[BH*Nq];
__device__ float g_sj[BH*Nq];
__device__ int   g_sel[BH*Kq];         // selected neighbor indices, ascending
__device__ float g_selv[BH*Kq];        // s_j at selected
__device__ float g_sjmax[BH];
__device__ float g_WhSel[BH*Kq*HD];    // gathered Wh rows

// ---------------------------------------------------------------------------
// Kernel 1: Wh = h @ W  (per head), plus s_i = Wh·a[:hd], s_j = Wh·a[hd:]
// Block: 128 threads (thread = output col c = h*32+d, warp == head), 16 rows.
// ---------------------------------------------------------------------------
__global__ void k1_wh(const float* __restrict__ h,
                      const float* __restrict__ W,
                      const float* __restrict__ a)
{
    __shared__ float hs[16][DIN];
    const int tid = threadIdx.x;          // 0..127
    const int hh  = tid >> 5;             // head (== warp id)
    const int d   = tid & 31;             // lane = feature within head
    const int row0 = blockIdx.x * 16;     // global row in [0, B*N)

    #pragma unroll
    for (int r = 0; r < 16; ++r)
        hs[r][tid] = h[(row0 + r) * DIN + tid];
    __syncthreads();

    float acc[16];
    #pragma unroll
    for (int r = 0; r < 16; ++r) acc[r] = 0.f;

    const float* Wcol = W + hh * DIN * HD + d;   // W[hh][f][d], stride 32 per f

    for (int f0 = 0; f0 < DIN; f0 += 16) {
        float wreg[16];
        #pragma unroll
        for (int ff = 0; ff < 16; ++ff)
            wreg[ff] = Wcol[(f0 + ff) * HD];
        #pragma unroll
        for (int r = 0; r < 16; ++r) {
            const float4* hp = (const float4*)&hs[r][f0];
            float4 h0 = hp[0], h1 = hp[1], h2 = hp[2], h3 = hp[3];
            float s = acc[r];
            s += h0.x*wreg[0];  s += h0.y*wreg[1];  s += h0.z*wreg[2];  s += h0.w*wreg[3];
            s += h1.x*wreg[4];  s += h1.y*wreg[5];  s += h1.z*wreg[6];  s += h1.w*wreg[7];
            s += h2.x*wreg[8];  s += h2.y*wreg[9];  s += h2.z*wreg[10]; s += h2.w*wreg[11];
            s += h3.x*wreg[12]; s += h3.y*wreg[13]; s += h3.z*wreg[14]; s += h3.w*wreg[15];
            acc[r] = s;
        }
    }

    const float ai = a[hh * 64 + d];
    const float aj = a[hh * 64 + 32 + d];
    const int b  = row0 >> 11;            // row0 / 2048
    const int n0 = row0 & 2047;
    const int bh = b * Hq + hh;

    #pragma unroll
    for (int r = 0; r < 16; ++r) {
        const int n = n0 + r;
        g_Wh[((size_t)bh * Nq + n) * HD + d] = acc[r];
        float si = acc[r] * ai;
        float sj = acc[r] * aj;
        #pragma unroll
        for (int o = 16; o; o >>= 1) {
            si += __shfl_down_sync(0xffffffffu, si, o);
            sj += __shfl_down_sync(0xffffffffu, sj, o);
        }
        if (d == 0) {
            g_si[bh * Nq + n] = si;
            g_sj[bh * Nq + n] = sj;
        }
    }
}

// ---------------------------------------------------------------------------
// Kernel 2: per (b,h) radix-select top-K of s_j (exact top_k tie semantics:
// values descending, ties by lowest index), build ascending-index selected
// list, gather Wh_sel. One block of 256 threads per (b,h).
// ---------------------------------------------------------------------------
__device__ __forceinline__ int block_exscan256(int v, int* wsum)
{
    __syncthreads();                       // protect wsum reuse
    const int lane = threadIdx.x & 31, w = threadIdx.x >> 5;
    int inc = v;
    #pragma unroll
    for (int o = 1; o < 32; o <<= 1) {
        int t = __shfl_up_sync(0xffffffffu, inc, o);
        if (lane >= o) inc += t;
    }
    if (lane == 31) wsum[w] = inc;
    __syncthreads();
    if (threadIdx.x == 0) {
        int s = 0;
        #pragma unroll
        for (int i = 0; i < 8; ++i) { int t = wsum[i]; wsum[i] = s; s += t; }
    }
    __syncthreads();
    return wsum[w] + inc - v;              // exclusive prefix
}

__global__ void k2_select()
{
    __shared__ unsigned uvals[Nq];
    __shared__ float    fvals[Nq];
    __shared__ int      hist[256];
    __shared__ int      wsum[8];
    __shared__ float    redf[8];
    __shared__ int      sel_s[Kq];
    __shared__ unsigned sh_pref;
    __shared__ int      sh_rem;

    const int bh  = blockIdx.x;
    const int tid = threadIdx.x;

    float mx = -3.4e38f;
    for (int j = tid; j < Nq; j += 256) {
        float v = g_sj[bh * Nq + j];
        fvals[j] = v;
        unsigned u = __float_as_uint(v);
        u = (u & 0x80000000u) ? ~u : (u | 0x80000000u);   // order-preserving map
        uvals[j] = u;
        mx = fmaxf(mx, v);
    }
    // block max reduce -> g_sjmax
    #pragma unroll
    for (int o = 16; o; o >>= 1) mx = fmaxf(mx, __shfl_down_sync(0xffffffffu, mx, o));
    if ((tid & 31) == 0) redf[tid >> 5] = mx;
    __syncthreads();
    if (tid == 0) {
        float m = redf[0];
        #pragma unroll
        for (int i = 1; i < 8; ++i) m = fmaxf(m, redf[i]);
        g_sjmax[bh] = m;
    }

    // radix select: find K-th largest (as ordered uint) + #ties to take
    unsigned prefix = 0;
    int remaining = Kq;
    for (int pass = 0; pass < 4; ++pass) {
        const int shift = 24 - 8 * pass;
        const unsigned mask_hi = (pass == 0) ? 0u : (0xFFFFFFFFu << (shift + 8));
        hist[tid] = 0;  // blockDim == 256
        __syncthreads();
        for (int j = tid; j < Nq; j += 256) {
            unsigned u = uvals[j];
            if ((u & mask_hi) == prefix)
                atomicAdd(&hist[(u >> shift) & 255], 1);
        }
        __syncthreads();
        if (tid == 0) {
            int accu = 0;
            for (int bb = 255; bb >= 0; --bb) {
                int c = hist[bb];
                if (accu + c >= remaining) {
                    sh_pref = prefix | ((unsigned)bb << shift);
                    sh_rem  = remaining - accu;
                    break;
                }
                accu += c;
            }
        }
        __syncthreads();
        prefix    = sh_pref;
        remaining = sh_rem;
        __syncthreads();
    }
    const unsigned tau = prefix;       // exact bits of K-th largest value
    const int tneed    = remaining;    // #elements == tau to take (lowest idx first)

    // per-thread local elements (8 contiguous)
    const int j0 = tid * 8;
    unsigned uloc[8];
    int myeq = 0;
    #pragma unroll
    for (int e = 0; e < 8; ++e) {
        uloc[e] = uvals[j0 + e];
        if (uloc[e] == tau) myeq++;
    }
    const int eqbase = block_exscan256(myeq, wsum);

    int flags = 0, cnt = 0, eqr = eqbase;
    #pragma unroll
    for (int e = 0; e < 8; ++e) {
        bool s;
        if (uloc[e] > tau)        s = true;
        else if (uloc[e] == tau) { s = (eqr < tneed); eqr++; }
        else                      s = false;
        if (s) { flags |= (1 << e); cnt++; }
    }
    int pos = block_exscan256(cnt, wsum);
    #pragma unroll
    for (int e = 0; e < 8; ++e) {
        if (flags & (1 << e)) {
            sel_s[pos]              = j0 + e;
            g_sel [bh * Kq + pos]   = j0 + e;
            g_selv[bh * Kq + pos]   = fvals[j0 + e];
            pos++;
        }
    }
    __syncthreads();

    // gather Wh_sel rows (contiguous 128B each)
    for (int idx = tid; idx < Kq * HD; idx += 256) {
        const int kk = idx >> 5, d = idx & 31;
        g_WhSel[((size_t)bh * Kq + kk) * HD + d] =
            g_Wh[((size_t)bh * Nq + sel_s[kk]) * HD + d];
    }
}

// ---------------------------------------------------------------------------
// Kernel 3: main pass. CTA = (b, 16-row tile), 256 threads = 8 warps.
// Warp task = (head, 8 rows): gather adj at selected cols, exp weights,
// Z-normalize, and [8 x 204] x [204 x 32] FMA with 8-row register blocking.
// ---------------------------------------------------------------------------
__global__ void k3_main(const float* __restrict__ adj, float* __restrict__ out)
{
    __shared__ float g_sm[8][8][32];     // [warp][row][kk-in-chunk]
    __shared__ int   sel_s [Hq][Kq];
    __shared__ float selv_s[Hq][Kq];
    __shared__ float sjm_s[Hq];

    const int tid  = threadIdx.x;
    const int w    = tid >> 5;
    const int lane = tid & 31;
    const int bx   = blockIdx.x;
    const int b    = bx >> 7;            // 128 tiles per batch
    const int i0   = (bx & 127) * 16;

    for (int idx = tid; idx < Hq * Kq; idx += 256) {
        const int hh = idx / Kq, kk = idx % Kq;
        sel_s [hh][kk] = g_sel [(b * Hq + hh) * Kq + kk];
        selv_s[hh][kk] = g_selv[(b * Hq + hh) * Kq + kk];
    }
    if (tid < Hq) sjm_s[tid] = g_sjmax[b * Hq + tid];
    __syncthreads();

    const int hh    = w & 3;
    const int rsub  = w >> 2;
    const int bh    = b * Hq + hh;
    const int ibase = i0 + rsub * 8;

    float si[8], m[8], zl[8], acc[8];
    #pragma unroll
    for (int r = 0; r < 8; ++r) {
        si[r] = g_si[bh * Nq + ibase + r];
        const float x = si[r] + sjm_s[hh];
        m[r]  = (x >= 0.f) ? x : 0.2f * x;
        zl[r] = 0.f;
        acc[r] = 0.f;
    }

    const float* adjb = adj + (size_t)b * Nq * Nq;
    const float* whg  = g_WhSel + (size_t)bh * Kq * HD;

    for (int c = 0; c < 7; ++c) {        // ceil(204/32) chunks
        const int kk    = c * 32 + lane;
        const bool valid = (kk < Kq);
        const float vj  = valid ? selv_s[hh][kk] : 0.f;
        const int   col = valid ? sel_s [hh][kk] : 0;

        #pragma unroll
        for (int r = 0; r < 8; ++r) {
            const float x = si[r] + vj;
            const float e = (x >= 0.f) ? x : 0.2f * x;
            const float p = valid ? __expf(e - m[r]) : 0.f;
            zl[r] += p;
            const float av = valid ? __ldg(&adjb[(size_t)(ibase + r) * Nq + col]) : 0.f;
            g_sm[w][r][lane] = p * av;
        }
        __syncwarp();

        #pragma unroll
        for (int k4 = 0; k4 < 32; k4 += 4) {
            float wv[4];
            #pragma unroll
            for (int u = 0; u < 4; ++u) {
                int kkk = c * 32 + k4 + u;
                kkk = (kkk < Kq) ? kkk : (Kq - 1);      // clamp; g==0 nullifies
                wv[u] = whg[kkk * HD + lane];
            }
            #pragma unroll
            for (int r = 0; r < 8; ++r) {
                const float4 gf = *(const float4*)&g_sm[w][r][k4];
                float s = acc[r];
                s += gf.x * wv[0];
                s += gf.y * wv[1];
                s += gf.z * wv[2];
                s += gf.w * wv[3];
                acc[r] = s;
            }
        }
        __syncwarp();
    }

    #pragma unroll
    for (int r = 0; r < 8; ++r) {
        float z = zl[r];
        #pragma unroll
        for (int o = 16; o; o >>= 1) z += __shfl_xor_sync(0xffffffffu, z, o);
        const float invz = 1.0f / z;
        out[(size_t)(b * Nq + ibase + r) * (Hq * HD) + hh * HD + lane] = acc[r] * invz;
    }
}

// ---------------------------------------------------------------------------
extern "C" void kernel_launch(void* const* d_in, const int* in_sizes, int n_in,
                              void* d_out, int out_size)
{
    const float *h = nullptr, *adj = nullptr, *W = nullptr, *a = nullptr;
    for (int i = 0; i < n_in; ++i) {
        switch (in_sizes[i]) {
            case Bq*Nq*DIN:  h   = (const float*)d_in[i]; break;  // 1048576
            case Bq*Nq*Nq:   adj = (const float*)d_in[i]; break;  // 16777216
            case Hq*DIN*HD:  W   = (const float*)d_in[i]; break;  // 16384
            case Hq*2*HD:    a   = (const float*)d_in[i]; break;  // 256
            default: break;
        }
    }
    float* out = (float*)d_out;

    k1_wh    <<<(Bq*Nq)/16, 128>>>(h, W, a);
    k2_select<<<BH, 256>>>();
    k3_main  <<<Bq * (Nq/16), 256>>>(adj, out);
}

// round 2
// speedup vs baseline: 1.0207x; 1.0207x over previous
#include <cuda_runtime.h>
#include <math.h>

// Problem constants (fixed shapes from reference)
#define Bq   4
#define Nq   2048
#define DIN  128
#define Hq   4
#define HD   32
#define Kq   204          // int(0.1 * 2048)
#define BH   (Bq*Hq)      // 16

// k3 split of the K dimension (static smem < 48KB)
#define KP1  104
#define KP2  100

// Scratch (device globals; no allocation allowed)
__device__ float g_Wh[BH*Nq*HD];       // [b][h][n][d]  4 MB
__device__ float g_si[BH*Nq];
__device__ float g_sj[BH*Nq];
__device__ int   g_sel[BH*Kq];         // selected neighbor indices, ascending
__device__ float g_selv[BH*Kq];        // s_j at selected
__device__ float g_sjmax[BH];
__device__ float g_WhSel[BH*Kq*HD];    // gathered Wh rows

// ---------------------------------------------------------------------------
// Kernel 1: Wh = h @ W  (per head), plus s_i = Wh·a[:hd], s_j = Wh·a[hd:]
// Block: 128 threads (thread = output col c = h*32+d, warp == head), 8 rows.
// ---------------------------------------------------------------------------
__global__ void k1_wh(const float* __restrict__ h,
                      const float* __restrict__ W,
                      const float* __restrict__ a)
{
    __shared__ float hs[8][DIN];
    const int tid = threadIdx.x;          // 0..127
    const int hh  = tid >> 5;             // head (== warp id)
    const int d   = tid & 31;             // lane = feature within head
    const int row0 = blockIdx.x * 8;      // global row in [0, B*N)

    #pragma unroll
    for (int r = 0; r < 8; ++r)
        hs[r][tid] = h[(row0 + r) * DIN + tid];
    __syncthreads();

    float acc[8];
    #pragma unroll
    for (int r = 0; r < 8; ++r) acc[r] = 0.f;

    const float* Wcol = W + hh * DIN * HD + d;   // W[hh][f][d], stride 32 per f

    for (int f0 = 0; f0 < DIN; f0 += 16) {
        float wreg[16];
        #pragma unroll
        for (int ff = 0; ff < 16; ++ff)
            wreg[ff] = Wcol[(f0 + ff) * HD];
        #pragma unroll
        for (int r = 0; r < 8; ++r) {
            const float4* hp = (const float4*)&hs[r][f0];
            float4 h0 = hp[0], h1 = hp[1], h2 = hp[2], h3 = hp[3];
            float s = acc[r];
            s += h0.x*wreg[0];  s += h0.y*wreg[1];  s += h0.z*wreg[2];  s += h0.w*wreg[3];
            s += h1.x*wreg[4];  s += h1.y*wreg[5];  s += h1.z*wreg[6];  s += h1.w*wreg[7];
            s += h2.x*wreg[8];  s += h2.y*wreg[9];  s += h2.z*wreg[10]; s += h2.w*wreg[11];
            s += h3.x*wreg[12]; s += h3.y*wreg[13]; s += h3.z*wreg[14]; s += h3.w*wreg[15];
            acc[r] = s;
        }
    }

    const float ai = a[hh * 64 + d];
    const float aj = a[hh * 64 + 32 + d];
    const int b  = row0 >> 11;            // row0 / 2048
    const int n0 = row0 & 2047;
    const int bh = b * Hq + hh;

    #pragma unroll
    for (int r = 0; r < 8; ++r) {
        const int n = n0 + r;
        g_Wh[((size_t)bh * Nq + n) * HD + d] = acc[r];
        float si = acc[r] * ai;
        float sj = acc[r] * aj;
        #pragma unroll
        for (int o = 16; o; o >>= 1) {
            si += __shfl_down_sync(0xffffffffu, si, o);
            sj += __shfl_down_sync(0xffffffffu, sj, o);
        }
        if (d == 0) {
            g_si[bh * Nq + n] = si;
            g_sj[bh * Nq + n] = sj;
        }
    }
}

// ---------------------------------------------------------------------------
// Kernel 2: per (b,h) radix-select top-K of s_j (exact top_k tie semantics:
// values descending, ties by lowest index), build ascending-index selected
// list, gather Wh_sel. One block of 256 threads per (b,h).
// ---------------------------------------------------------------------------
__device__ __forceinline__ int block_exscan256(int v, int* wsum)
{
    __syncthreads();                       // protect wsum reuse
    const int lane = threadIdx.x & 31, w = threadIdx.x >> 5;
    int inc = v;
    #pragma unroll
    for (int o = 1; o < 32; o <<= 1) {
        int t = __shfl_up_sync(0xffffffffu, inc, o);
        if (lane >= o) inc += t;
    }
    if (lane == 31) wsum[w] = inc;
    __syncthreads();
    if (threadIdx.x == 0) {
        int s = 0;
        #pragma unroll
        for (int i = 0; i < 8; ++i) { int t = wsum[i]; wsum[i] = s; s += t; }
    }
    __syncthreads();
    return wsum[w] + inc - v;              // exclusive prefix
}

__global__ void k2_select()
{
    __shared__ unsigned uvals[Nq];
    __shared__ float    fvals[Nq];
    __shared__ int      hist[256];
    __shared__ int      wsum[8];
    __shared__ float    redf[8];
    __shared__ int      sel_s[Kq];
    __shared__ unsigned sh_pref;
    __shared__ int      sh_rem;

    const int bh  = blockIdx.x;
    const int tid = threadIdx.x;

    float mx = -3.4e38f;
    for (int j = tid; j < Nq; j += 256) {
        float v = g_sj[bh * Nq + j];
        fvals[j] = v;
        unsigned u = __float_as_uint(v);
        u = (u & 0x80000000u) ? ~u : (u | 0x80000000u);   // order-preserving map
        uvals[j] = u;
        mx = fmaxf(mx, v);
    }
    // block max reduce -> g_sjmax
    #pragma unroll
    for (int o = 16; o; o >>= 1) mx = fmaxf(mx, __shfl_down_sync(0xffffffffu, mx, o));
    if ((tid & 31) == 0) redf[tid >> 5] = mx;
    __syncthreads();
    if (tid == 0) {
        float m = redf[0];
        #pragma unroll
        for (int i = 1; i < 8; ++i) m = fmaxf(m, redf[i]);
        g_sjmax[bh] = m;
    }

    // radix select: find K-th largest (as ordered uint) + #ties to take
    unsigned prefix = 0;
    int remaining = Kq;
    for (int pass = 0; pass < 4; ++pass) {
        const int shift = 24 - 8 * pass;
        const unsigned mask_hi = (pass == 0) ? 0u : (0xFFFFFFFFu << (shift + 8));
        hist[tid] = 0;  // blockDim == 256
        __syncthreads();
        for (int j = tid; j < Nq; j += 256) {
            unsigned u = uvals[j];
            if ((u & mask_hi) == prefix)
                atomicAdd(&hist[(u >> shift) & 255], 1);
        }
        __syncthreads();
        if (tid == 0) {
            int accu = 0;
            for (int bb = 255; bb >= 0; --bb) {
                int c = hist[bb];
                if (accu + c >= remaining) {
                    sh_pref = prefix | ((unsigned)bb << shift);
                    sh_rem  = remaining - accu;
                    break;
                }
                accu += c;
            }
        }
        __syncthreads();
        prefix    = sh_pref;
        remaining = sh_rem;
        __syncthreads();
    }
    const unsigned tau = prefix;       // exact bits of K-th largest value
    const int tneed    = remaining;    // #elements == tau to take (lowest idx first)

    // per-thread local elements (8 contiguous)
    const int j0 = tid * 8;
    unsigned uloc[8];
    int myeq = 0;
    #pragma unroll
    for (int e = 0; e < 8; ++e) {
        uloc[e] = uvals[j0 + e];
        if (uloc[e] == tau) myeq++;
    }
    const int eqbase = block_exscan256(myeq, wsum);

    int flags = 0, cnt = 0, eqr = eqbase;
    #pragma unroll
    for (int e = 0; e < 8; ++e) {
        bool s;
        if (uloc[e] > tau)        s = true;
        else if (uloc[e] == tau) { s = (eqr < tneed); eqr++; }
        else                      s = false;
        if (s) { flags |= (1 << e); cnt++; }
    }
    int pos = block_exscan256(cnt, wsum);
    #pragma unroll
    for (int e = 0; e < 8; ++e) {
        if (flags & (1 << e)) {
            sel_s[pos]              = j0 + e;
            g_sel [bh * Kq + pos]   = j0 + e;
            g_selv[bh * Kq + pos]   = fvals[j0 + e];
            pos++;
        }
    }
    __syncthreads();

    // gather Wh_sel rows (contiguous 128B each)
    for (int idx = tid; idx < Kq * HD; idx += 256) {
        const int kk = idx >> 5, d = idx & 31;
        g_WhSel[((size_t)bh * Kq + kk) * HD + d] =
            g_Wh[((size_t)bh * Nq + sel_s[kk]) * HD + d];
    }
}

// ---------------------------------------------------------------------------
// Kernel 3: main pass, phase-separated.
// CTA = (b, h, 32-row tile), 256 threads = 8 warps.
//   Phase A: load sel/selv, Wh_sel -> smem; si, m per row.
//   Phase B (x2, k halves): massively-parallel adj gather: thread = (row, k%8),
//            26 independent LDGs, p = exp(LR(si+sj)-m), wts = p*adj, z += p.
//   Phase C (x2): smem GEMM, warp = 4 rows x 32 cols, 4-k unroll.
// ---------------------------------------------------------------------------
__global__ void __launch_bounds__(256) k3_main(const float* __restrict__ adj,
                                               float* __restrict__ out)
{
    __shared__ __align__(16) float whs[Kq * HD];    // 26112 B  [k][d]
    __shared__ __align__(16) float wts[32 * KP1];   // 13312 B  [r][k-local]
    __shared__ int   sel_s[Kq];
    __shared__ float selv_s[Kq];
    __shared__ float si_s[32], m_s[32], z_s[32];

    const int tid  = threadIdx.x;
    const int lane = tid & 31;
    const int w    = tid >> 5;

    // block index: ((b*64 + tile)*4 + hh) so 4 heads of a row-tile are adjacent
    const int hh   = blockIdx.x & 3;
    const int tile = (blockIdx.x >> 2) & 63;
    const int b    = blockIdx.x >> 8;
    const int bh   = b * Hq + hh;
    const int i0   = tile * 32;

    // Phase A: stage selection + Wh_sel
    for (int k = tid; k < Kq; k += 256) {
        sel_s [k] = g_sel [bh * Kq + k];
        selv_s[k] = g_selv[bh * Kq + k];
    }
    {
        const float4* src = (const float4*)(g_WhSel + (size_t)bh * Kq * HD);
        float4* dst = (float4*)whs;
        for (int idx = tid; idx < Kq * HD / 4; idx += 256)
            dst[idx] = src[idx];
    }
    if (tid < 32) {
        const float sjm = g_sjmax[bh];
        const float si  = g_si[bh * Nq + i0 + tid];
        si_s[tid] = si;
        const float x = si + sjm;
        m_s[tid] = (x >= 0.f) ? x : 0.2f * x;
    }
    __syncthreads();

    // thread mapping for gather phases: row = tid>>3, k-slot = tid&7
    const int gr = tid >> 3;            // 0..31
    const int gk = tid & 7;
    const float* adjrow = adj + (size_t)b * Nq * Nq + (size_t)(i0 + gr) * Nq;
    const float gsi = si_s[gr];
    const float gm  = m_s[gr];
    float zloc = 0.f;

    float accv[4];                       // GEMM accumulators (4 rows x lane col)
    #pragma unroll
    for (int r = 0; r < 4; ++r) accv[r] = 0.f;
    const int r0 = w * 4;

    #pragma unroll
    for (int pass = 0; pass < 2; ++pass) {
        const int kbase = pass ? KP1 : 0;
        const int kcnt  = pass ? KP2 : KP1;

        // ---- Phase B: gather + weights ----
        for (int k = kbase + gk; k < kbase + kcnt; k += 8) {
            const float vj = selv_s[k];
            const int  col = sel_s[k];
            const float av = __ldg(&adjrow[col]);
            const float x  = gsi + vj;
            const float e  = (x >= 0.f) ? x : 0.2f * x;
            const float p  = __expf(e - gm);
            zloc += p;
            wts[gr * KP1 + (k - kbase)] = p * av;
        }
        __syncthreads();

        // ---- Phase C: GEMM from smem ----
        for (int k0 = 0; k0 < kcnt; k0 += 4) {
            float whv[4];
            #pragma unroll
            for (int u = 0; u < 4; ++u)
                whv[u] = whs[(kbase + k0 + u) * HD + lane];
            #pragma unroll
            for (int r = 0; r < 4; ++r) {
                const float4 g = *(const float4*)&wts[(r0 + r) * KP1 + k0];
                float s = accv[r];
                s += g.x * whv[0];
                s += g.y * whv[1];
                s += g.z * whv[2];
                s += g.w * whv[3];
                accv[r] = s;
            }
        }
        __syncthreads();
    }

    // z reduce over the 8 threads sharing a row (lanes gk 0..7)
    float z = zloc;
    z += __shfl_xor_sync(0xffffffffu, z, 1);
    z += __shfl_xor_sync(0xffffffffu, z, 2);
    z += __shfl_xor_sync(0xffffffffu, z, 4);
    if (gk == 0) z_s[gr] = z;
    __syncthreads();

    #pragma unroll
    for (int r = 0; r < 4; ++r) {
        const float invz = 1.0f / z_s[r0 + r];
        out[(size_t)(b * Nq + i0 + r0 + r) * (Hq * HD) + hh * HD + lane] =
            accv[r] * invz;
    }
}

// ---------------------------------------------------------------------------
extern "C" void kernel_launch(void* const* d_in, const int* in_sizes, int n_in,
                              void* d_out, int out_size)
{
    const float *h = nullptr, *adj = nullptr, *W = nullptr, *a = nullptr;
    for (int i = 0; i < n_in; ++i) {
        switch (in_sizes[i]) {
            case Bq*Nq*DIN:  h   = (const float*)d_in[i]; break;  // 1048576
            case Bq*Nq*Nq:   adj = (const float*)d_in[i]; break;  // 16777216
            case Hq*DIN*HD:  W   = (const float*)d_in[i]; break;  // 16384
            case Hq*2*HD:    a   = (const float*)d_in[i]; break;  // 256
            default: break;
        }
    }
    float* out = (float*)d_out;

    k1_wh    <<<(Bq*Nq)/8, 128>>>(h, W, a);
    k2_select<<<BH, 256>>>();
    k3_main  <<<Bq * Hq * (Nq/32), 256>>>(adj, out);
}

// round 3
// speedup vs baseline: 1.1144x; 1.0918x over previous
#include <cuda_runtime.h>
#include <math.h>

// Problem constants (fixed shapes from reference)
#define Bq   4
#define Nq   2048
#define DIN  128
#define Hq   4
#define HD   32
#define Kq   204          // int(0.1 * 2048)
#define KPAD 224          // padded K (multiple of 32)
#define BH   (Bq*Hq)      // 16

// Scratch (device globals; zero-initialized, no allocation allowed)
__device__ float g_Wh[BH*Nq*HD];          // [bh][n][d]  4 MB
__device__ float g_si[BH*Nq];
__device__ float g_sj[BH*Nq];
__device__ int   g_sel[BH*Kq];            // selected neighbor cols, ascending
__device__ float g_selv[BH*KPAD];         // s_j at selected (+ -3e38 pads)
__device__ float g_sjmax[BH];
__device__ float g_WhSel[BH*KPAD*HD];     // gathered Wh rows (pads stay 0)
__device__ float g_adjsel[(size_t)BH*Nq*KPAD];  // compacted adj cols (29 MB)

// ---------------------------------------------------------------------------
// Kernel 1: Wh = h @ W (per head) + s_i, s_j epilogue.
// CTA: 32 rows, 256 threads. Warp w owns rows w*4..w*4+3; lane = d;
// each thread computes 4 rows x 4 heads (col = h*32+d). W staged via smem.
// ---------------------------------------------------------------------------
__global__ void __launch_bounds__(256) k1_wh(const float* __restrict__ h,
                                             const float* __restrict__ W,
                                             const float* __restrict__ a)
{
    __shared__ float hs[32][DIN];     // 16 KB
    __shared__ float Ws[32][DIN];     // 16 KB  [f][h*32+d]
    const int tid = threadIdx.x;
    const int w   = tid >> 5;
    const int d   = tid & 31;
    const int row0 = blockIdx.x * 32;

    #pragma unroll
    for (int i = 0; i < 4; ++i) {
        const int id = tid + i * 256;
        ((float4*)hs)[id] = ((const float4*)(h + (size_t)row0 * DIN))[id];
    }

    float acc[4][4];
    #pragma unroll
    for (int r = 0; r < 4; ++r)
        #pragma unroll
        for (int c = 0; c < 4; ++c) acc[r][c] = 0.f;

    for (int chunk = 0; chunk < 4; ++chunk) {
        __syncthreads();
        #pragma unroll
        for (int i = 0; i < 16; ++i) {
            const int idx = tid + i * 256;
            const int h_ = idx >> 10, f = (idx >> 5) & 31, dd = idx & 31;
            Ws[f][h_ * 32 + dd] = W[h_ * (DIN*HD) + (chunk * 32 + f) * HD + dd];
        }
        __syncthreads();

        #pragma unroll
        for (int f4 = 0; f4 < 32; f4 += 4) {
            float hvf[4][4];
            #pragma unroll
            for (int r = 0; r < 4; ++r) {
                const float4 t = *(const float4*)&hs[w * 4 + r][chunk * 32 + f4];
                hvf[r][0] = t.x; hvf[r][1] = t.y; hvf[r][2] = t.z; hvf[r][3] = t.w;
            }
            #pragma unroll
            for (int u = 0; u < 4; ++u) {
                const float wv0 = Ws[f4+u][d];
                const float wv1 = Ws[f4+u][32+d];
                const float wv2 = Ws[f4+u][64+d];
                const float wv3 = Ws[f4+u][96+d];
                #pragma unroll
                for (int r = 0; r < 4; ++r) {
                    acc[r][0] += hvf[r][u] * wv0;
                    acc[r][1] += hvf[r][u] * wv1;
                    acc[r][2] += hvf[r][u] * wv2;
                    acc[r][3] += hvf[r][u] * wv3;
                }
            }
        }
    }

    const int b     = row0 >> 11;
    const int nbase = (row0 & 2047) + w * 4;
    #pragma unroll
    for (int hh = 0; hh < 4; ++hh) {
        const float ai = a[hh * 64 + d];
        const float aj = a[hh * 64 + 32 + d];
        const int bh = b * Hq + hh;
        #pragma unroll
        for (int r = 0; r < 4; ++r) {
            const float val = acc[r][hh];
            g_Wh[((size_t)bh * Nq + nbase + r) * HD + d] = val;
            float si = val * ai, sj = val * aj;
            #pragma unroll
            for (int o = 16; o; o >>= 1) {
                si += __shfl_xor_sync(0xffffffffu, si, o);
                sj += __shfl_xor_sync(0xffffffffu, sj, o);
            }
            if (d == 0) {
                g_si[bh * Nq + nbase + r] = si;
                g_sj[bh * Nq + nbase + r] = sj;
            }
        }
    }
}

// ---------------------------------------------------------------------------
// Kernel 2: per (b,h) radix-select top-K of s_j (exact jax top_k semantics:
// descending values, ties by lowest index). Parallel bin-find (no serial scan).
// ---------------------------------------------------------------------------
__device__ __forceinline__ int block_incscan256(int v, int* wsum)
{
    __syncthreads();
    const int lane = threadIdx.x & 31, w = threadIdx.x >> 5;
    int inc = v;
    #pragma unroll
    for (int o = 1; o < 32; o <<= 1) {
        const int t = __shfl_up_sync(0xffffffffu, inc, o);
        if (lane >= o) inc += t;
    }
    if (lane == 31) wsum[w] = inc;
    __syncthreads();
    if (threadIdx.x == 0) {
        int s = 0;
        #pragma unroll
        for (int i = 0; i < 8; ++i) { const int t = wsum[i]; wsum[i] = s; s += t; }
    }
    __syncthreads();
    return inc + wsum[w];                   // inclusive scan
}

__device__ __forceinline__ int block_exscan256(int v, int* wsum)
{
    return block_incscan256(v, wsum) - v;
}

__global__ void __launch_bounds__(256) k2_select()
{
    __shared__ unsigned uvals[Nq];
    __shared__ float    fvals[Nq];
    __shared__ int      hist[256];
    __shared__ int      wsum[8];
    __shared__ float    redf[8];
    __shared__ int      sel_s[Kq];
    __shared__ unsigned sh_pref;
    __shared__ int      sh_rem;

    const int bh  = blockIdx.x;
    const int tid = threadIdx.x;

    float mx = -3.4e38f;
    for (int j = tid; j < Nq; j += 256) {
        const float v = g_sj[bh * Nq + j];
        fvals[j] = v;
        unsigned u = __float_as_uint(v);
        u = (u & 0x80000000u) ? ~u : (u | 0x80000000u);
        uvals[j] = u;
        mx = fmaxf(mx, v);
    }
    #pragma unroll
    for (int o = 16; o; o >>= 1) mx = fmaxf(mx, __shfl_down_sync(0xffffffffu, mx, o));
    if ((tid & 31) == 0) redf[tid >> 5] = mx;
    __syncthreads();
    if (tid == 0) {
        float m = redf[0];
        #pragma unroll
        for (int i = 1; i < 8; ++i) m = fmaxf(m, redf[i]);
        g_sjmax[bh] = m;
    }

    unsigned prefix = 0;
    int remaining = Kq;
    for (int pass = 0; pass < 4; ++pass) {
        const int shift = 24 - 8 * pass;
        const unsigned mask_hi = (pass == 0) ? 0u : (0xFFFFFFFFu << (shift + 8));
        hist[tid] = 0;
        __syncthreads();
        for (int j = tid; j < Nq; j += 256) {
            const unsigned u = uvals[j];
            if ((u & mask_hi) == prefix)
                atomicAdd(&hist[(u >> shift) & 255], 1);
        }
        __syncthreads();
        // parallel bin-find: S[bin] = count in bins >= bin; bin = 255 - tid
        const int x = hist[255 - tid];
        const int incl = block_incscan256(x, wsum);   // = S[255 - tid]
        if (incl >= remaining && (incl - x) < remaining) {
            sh_pref = prefix | ((unsigned)(255 - tid) << shift);
            sh_rem  = remaining - (incl - x);
        }
        __syncthreads();
        prefix    = sh_pref;
        remaining = sh_rem;
        __syncthreads();
    }
    const unsigned tau = prefix;
    const int tneed    = remaining;

    const int j0 = tid * 8;
    unsigned uloc[8];
    int myeq = 0;
    #pragma unroll
    for (int e = 0; e < 8; ++e) {
        uloc[e] = uvals[j0 + e];
        if (uloc[e] == tau) myeq++;
    }
    const int eqbase = block_exscan256(myeq, wsum);

    int flags = 0, cnt = 0, eqr = eqbase;
    #pragma unroll
    for (int e = 0; e < 8; ++e) {
        bool s;
        if (uloc[e] > tau)        s = true;
        else if (uloc[e] == tau) { s = (eqr < tneed); eqr++; }
        else                      s = false;
        if (s) { flags |= (1 << e); cnt++; }
    }
    int pos = block_exscan256(cnt, wsum);
    #pragma unroll
    for (int e = 0; e < 8; ++e) {
        if (flags & (1 << e)) {
            sel_s[pos]               = j0 + e;
            g_sel [bh * Kq + pos]    = j0 + e;
            g_selv[bh * KPAD + pos]  = fvals[j0 + e];
            pos++;
        }
    }
    // pads so k3 computes p ~ 0 there
    if (tid >= Kq && tid < KPAD) g_selv[bh * KPAD + tid] = -3.0e38f;
    __syncthreads();

    // gather Wh_sel rows (g_WhSel pads remain 0 from static init)
    for (int idx = tid; idx < Kq * HD; idx += 256) {
        const int kk = idx >> 5, d = idx & 31;
        g_WhSel[((size_t)bh * KPAD + kk) * HD + d] =
            g_Wh[((size_t)bh * Nq + sel_s[kk]) * HD + d];
    }
}

// ---------------------------------------------------------------------------
// Kernel g1: compact adj columns. CTA = (b, 8 rows), 256 threads (warp = row).
// Reads adj rows fully coalesced once; per-column byte map (col -> k, 4 heads
// packed in one uint32) routes selected values into smem row buffers; writes
// g_adjsel coalesced. Non-selected/pad slots stay 0.
// ---------------------------------------------------------------------------
__global__ void __launch_bounds__(256) g1_gather(const float* __restrict__ adj)
{
    __shared__ unsigned char cmapb[Nq * 4];          // 8 KB   [col][h]
    __shared__ float rowbuf[8][Hq][KPAD];            // 28.7 KB

    const int tid  = threadIdx.x;
    const int w    = tid >> 5;
    const int lane = tid & 31;
    const int b    = blockIdx.x >> 8;
    const int row0 = (blockIdx.x & 255) * 8;

    #pragma unroll
    for (int i = 0; i < 8; ++i)
        ((unsigned*)cmapb)[tid + i * 256] = 0xFFFFFFFFu;
    #pragma unroll
    for (int i = 0; i < 28; ++i)
        ((float*)rowbuf)[tid + i * 256] = 0.f;
    __syncthreads();

    for (int idx = tid; idx < Hq * Kq; idx += 256) {
        const int hh = idx / Kq, k = idx - hh * Kq;
        const int col = g_sel[(b * Hq + hh) * Kq + k];
        cmapb[col * 4 + hh] = (unsigned char)k;
    }
    __syncthreads();

    const float4* arow = (const float4*)(adj + (size_t)b * Nq * Nq + (size_t)(row0 + w) * Nq);
    const uint4*  cmv4 = (const uint4*)cmapb;

    #pragma unroll
    for (int it = 0; it < 16; ++it) {
        const int q = it * 32 + lane;          // float4 index: cols 4q..4q+3
        const float4 av = arow[q];
        const uint4  cm = cmv4[q];
        const float  avf[4] = {av.x, av.y, av.z, av.w};
        const unsigned cmw[4] = {cm.x, cm.y, cm.z, cm.w};
        #pragma unroll
        for (int c = 0; c < 4; ++c) {
            #pragma unroll
            for (int hh = 0; hh < 4; ++hh) {
                const unsigned kk = (cmw[c] >> (8 * hh)) & 255u;
                if (kk != 255u) rowbuf[w][hh][kk] = avf[c];
            }
        }
    }
    __syncthreads();

    // write out: [r][hh][KPAD] -> g_adjsel[(b*4+hh)*Nq + row0+r][KPAD]
    #pragma unroll
    for (int i = 0; i < 7; ++i) {
        const int idx = tid + i * 256;          // float4 idx over 8*4*56
        const int rh = idx / 56, qq = idx - rh * 56;
        const int r = rh >> 2, hh = rh & 3;
        ((float4*)g_adjsel)[((size_t)(b * Hq + hh) * Nq + row0 + r) * (KPAD/4) + qq] =
            ((const float4*)rowbuf)[idx];
    }
}

// ---------------------------------------------------------------------------
// Kernel 3: main pass. CTA = (b, h, 16 rows), 128 threads.
//   B: coalesced read of adjsel + p = exp(LR(si+sj)-m), wts = p*adj (smem).
//   C: smem GEMM [16 x 224] x [224 x 32], warp = 4 rows x 32 cols.
// ---------------------------------------------------------------------------
__global__ void __launch_bounds__(128) k3_main(float* __restrict__ out)
{
    __shared__ __align__(16) float whs[KPAD][HD];        // 28672 B [k][d]
    __shared__ __align__(16) float wts[16][KPAD + 4];    // 14592 B
    __shared__ __align__(16) float selv_s[KPAD];
    __shared__ float si_s[16], m_s[16], z_s[16];

    const int tid  = threadIdx.x;
    const int lane = tid & 31;
    const int w    = tid >> 5;

    const int hh   = blockIdx.x & 3;
    const int tile = (blockIdx.x >> 2) & 127;
    const int b    = blockIdx.x >> 9;
    const int bh   = b * Hq + hh;
    const int i0   = tile * 16;

    #pragma unroll
    for (int i = 0; i < 14; ++i) {
        const int idx = tid + i * 128;
        ((float4*)whs)[idx] = ((const float4*)(g_WhSel + (size_t)bh * KPAD * HD))[idx];
    }
    if (tid < KPAD - 128) selv_s[128 + tid] = g_selv[bh * KPAD + 128 + tid];
    selv_s[tid] = g_selv[bh * KPAD + tid];
    if (tid < 16) {
        const float sjm = g_sjmax[bh];
        const float si  = g_si[bh * Nq + i0 + tid];
        si_s[tid] = si;
        const float x = si + sjm;
        m_s[tid] = (x >= 0.f) ? x : 0.2f * x;
    }
    __syncthreads();

    // Phase B: 8 threads per row, fully coalesced float4 sweep
    {
        const int gr = tid >> 3;          // 0..15
        const int gk = tid & 7;
        const float4* arow = (const float4*)(g_adjsel + ((size_t)bh * Nq + i0 + gr) * KPAD);
        const float gsi = si_s[gr];
        const float gm  = m_s[gr];
        float zloc = 0.f;

        #pragma unroll
        for (int it = 0; it < 7; ++it) {
            const int q = it * 8 + gk;          // 0..55
            const float4 av = arow[q];
            const float4 vj = ((const float4*)selv_s)[q];
            float4 pa;
            float x, e, p;
            x = gsi + vj.x; e = (x >= 0.f) ? x : 0.2f*x; p = __expf(e - gm); zloc += p; pa.x = p * av.x;
            x = gsi + vj.y; e = (x >= 0.f) ? x : 0.2f*x; p = __expf(e - gm); zloc += p; pa.y = p * av.y;
            x = gsi + vj.z; e = (x >= 0.f) ? x : 0.2f*x; p = __expf(e - gm); zloc += p; pa.z = p * av.z;
            x = gsi + vj.w; e = (x >= 0.f) ? x : 0.2f*x; p = __expf(e - gm); zloc += p; pa.w = p * av.w;
            *(float4*)&wts[gr][q * 4] = pa;
        }
        float z = zloc;
        z += __shfl_xor_sync(0xffffffffu, z, 1);
        z += __shfl_xor_sync(0xffffffffu, z, 2);
        z += __shfl_xor_sync(0xffffffffu, z, 4);
        if (gk == 0) z_s[gr] = z;
    }
    __syncthreads();

    // Phase C: warp = 4 rows x 32 cols
    const int r0 = w * 4;
    float accv[4] = {0.f, 0.f, 0.f, 0.f};
    for (int k0 = 0; k0 < KPAD; k0 += 4) {
        float whv[4];
        #pragma unroll
        for (int u = 0; u < 4; ++u) whv[u] = whs[k0 + u][lane];
        #pragma unroll
        for (int r = 0; r < 4; ++r) {
            const float4 g = *(const float4*)&wts[r0 + r][k0];
            float s = accv[r];
            s += g.x * whv[0];
            s += g.y * whv[1];
            s += g.z * whv[2];
            s += g.w * whv[3];
            accv[r] = s;
        }
    }

    #pragma unroll
    for (int r = 0; r < 4; ++r) {
        const float invz = 1.0f / z_s[r0 + r];
        out[(size_t)(b * Nq + i0 + r0 + r) * (Hq * HD) + hh * HD + lane] = accv[r] * invz;
    }
}

// ---------------------------------------------------------------------------
extern "C" void kernel_launch(void* const* d_in, const int* in_sizes, int n_in,
                              void* d_out, int out_size)
{
    const float *h = nullptr, *adj = nullptr, *W = nullptr, *a = nullptr;
    for (int i = 0; i < n_in; ++i) {
        switch (in_sizes[i]) {
            case Bq*Nq*DIN:  h   = (const float*)d_in[i]; break;  // 1048576
            case Bq*Nq*Nq:   adj = (const float*)d_in[i]; break;  // 16777216
            case Hq*DIN*HD:  W   = (const float*)d_in[i]; break;  // 16384
            case Hq*2*HD:    a   = (const float*)d_in[i]; break;  // 256
            default: break;
        }
    }
    float* out = (float*)d_out;

    k1_wh    <<<(Bq*Nq)/32, 256>>>(h, W, a);
    k2_select<<<BH, 256>>>();
    g1_gather<<<Bq * (Nq/8), 256>>>(adj);
    k3_main  <<<Bq * Hq * (Nq/16), 128>>>(out);
}